// round 4
// baseline (speedup 1.0000x reference)
#include <cuda_runtime.h>

#define ED 12
#define FF 24
#define SQ 8
#define VO 128
#define BPB 32            // batch elements per block
#define NTHREADS 256
#define KSTR 16           // K/V row stride (floats) — 64B rows, LDS.128-friendly
#define KBAT 132          // K/V batch stride (floats) = 8*16 + 4 pad -> distinct banks per bl

typedef unsigned long long u64;

__device__ __forceinline__ u64 pack2(float lo, float hi) {
    u64 r;
    asm("mov.b64 %0, {%1, %2};" : "=l"(r) : "f"(lo), "f"(hi));
    return r;
}
__device__ __forceinline__ void unpack2(u64 u, float& lo, float& hi) {
    asm("mov.b64 {%0, %1}, %2;" : "=f"(lo), "=f"(hi) : "l"(u));
}
__device__ __forceinline__ u64 fma2(u64 a, u64 b, u64 c) {
    u64 r;
    asm("fma.rn.f32x2 %0, %1, %2, %3;" : "=l"(r) : "l"(a), "l"(b), "l"(c));
    return r;
}
__device__ __forceinline__ float hsum2(u64 u) {
    float lo, hi; unpack2(u, lo, hi); return lo + hi;
}

// Precomputed tables: EWq|EWk|EWv [128][12] then PWq|PWk|PWv [8][12] (bias folded into PW)
__device__ __align__(16) float gTab[3 * VO * ED + 3 * SQ * ED];

// 24 blocks: block = m*8 + chunk; each handles 16 vocab rows of EW[m]; chunk 0 also does PW[m].
__global__ void precompute_tables(const float* __restrict__ embed,
                                  const float* __restrict__ pos,
                                  const float* __restrict__ Wq, const float* __restrict__ bq,
                                  const float* __restrict__ Wk, const float* __restrict__ bk,
                                  const float* __restrict__ Wv, const float* __restrict__ bv)
{
    const int m = blockIdx.x >> 3;        // 0=q, 1=k, 2=v
    const int chunk = blockIdx.x & 7;     // 16 vocab rows each
    const float* W = (m == 0) ? Wq : (m == 1) ? Wk : Wv;
    const float* b = (m == 0) ? bq : (m == 1) ? bk : bv;
    float* EW = gTab + m * VO * ED;
    float* PW = gTab + 3 * VO * ED + m * SQ * ED;
    const int base = chunk * 16 * ED;     // 192 outputs per chunk
    for (int idx = threadIdx.x; idx < 16 * ED; idx += blockDim.x) {
        const int v = (base + idx) / ED, i = (base + idx) % ED;
        float a = 0.f;
        #pragma unroll
        for (int d = 0; d < ED; d++) a = fmaf(embed[v * ED + d], W[i * ED + d], a);
        EW[base + idx] = a;
    }
    if (chunk == 0) {
        for (int idx = threadIdx.x; idx < SQ * ED; idx += blockDim.x) {
            const int n = idx / ED, i = idx % ED;
            float a = b[i];
            #pragma unroll
            for (int d = 0; d < ED; d++) a = fmaf(pos[n * ED + d], W[i * ED + d], a);
            PW[idx] = a;
        }
    }
}

__global__ __launch_bounds__(NTHREADS, 4)
void tiny_tf_kernel(const int* __restrict__ x,
                    const float* __restrict__ embed,
                    const float* __restrict__ pos,
                    const float* __restrict__ Wo, const float* __restrict__ bo,
                    const float* __restrict__ W1, const float* __restrict__ b1,
                    const float* __restrict__ W2, const float* __restrict__ b2,
                    const float* __restrict__ blm,
                    float* __restrict__ out)
{
    __shared__ __align__(16) float sPos[SQ * ED];
    __shared__ __align__(16) float sPW[3 * SQ * ED];     // bias-folded pos projections
    __shared__ __align__(16) float sWo[ED * ED];
    __shared__ __align__(16) float sW1[FF * ED];
    __shared__ __align__(16) float sW2[ED * FF];
    __shared__ float sbo[ED], sb1[FF], sb2[ED];
    __shared__ float sblm[VO];
    // K then V, each [32 batches][8 rows x 16 floats + 4 pad]; K region later aliased
    // for the final-X token matrix (needs 3072 floats; K region is 4224).
    __shared__ __align__(16) float sKV[2 * BPB * KBAT];  // 8448 floats = 33792 B

    const int tid = threadIdx.x;
    const float* __restrict__ tEW = gTab;

    // ---- cooperative staging ----
    for (int i = tid; i < SQ * ED; i += NTHREADS) sPos[i] = pos[i];
    for (int i = tid; i < 3 * SQ * ED; i += NTHREADS) sPW[i] = gTab[3 * VO * ED + i];
    for (int i = tid; i < ED * ED; i += NTHREADS) sWo[i] = Wo[i];
    for (int i = tid; i < FF * ED; i += NTHREADS) { sW1[i] = W1[i]; sW2[i] = W2[i]; }
    if (tid < ED) { sbo[tid] = bo[tid]; sb2[tid] = b2[tid]; }
    if (tid < FF) sb1[tid] = b1[tid];
    if (tid < VO) sblm[tid] = blm[tid];
    __syncthreads();

    const int bl = tid >> 3;   // local batch 0..31
    const int n  = tid & 7;    // token position 0..7
    const int b  = blockIdx.x * BPB + bl;

    const int tok = x[b * SQ + n];

    // ---- X = E[tok] + pos[n]  (E row via LDG.128, L1-hot) ----
    float X[ED];
    {
        const float4* Er = reinterpret_cast<const float4*>(embed + tok * ED);
        const float4* Pr = reinterpret_cast<const float4*>(sPos + n * ED);
        #pragma unroll
        for (int q = 0; q < 3; q++) {
            const float4 e = Er[q], p = Pr[q];
            X[4 * q + 0] = e.x + p.x; X[4 * q + 1] = e.y + p.y;
            X[4 * q + 2] = e.z + p.z; X[4 * q + 3] = e.w + p.w;
        }
    }

    // ---- Q/K/V via tables: proj = EW[tok] + PW[n] ----
    u64 qp[ED / 2];
    float* myK = &sKV[bl * KBAT + n * KSTR];
    float* myV = &sKV[BPB * KBAT + bl * KBAT + n * KSTR];
    {
        const float4* EQ = reinterpret_cast<const float4*>(tEW + 0 * VO * ED + tok * ED);
        const float4* EK = reinterpret_cast<const float4*>(tEW + 1 * VO * ED + tok * ED);
        const float4* EV = reinterpret_cast<const float4*>(tEW + 2 * VO * ED + tok * ED);
        const float4* PQ = reinterpret_cast<const float4*>(sPW + 0 * SQ * ED + n * ED);
        const float4* PK = reinterpret_cast<const float4*>(sPW + 1 * SQ * ED + n * ED);
        const float4* PV = reinterpret_cast<const float4*>(sPW + 2 * SQ * ED + n * ED);
        float4* kd = reinterpret_cast<float4*>(myK);
        float4* vd = reinterpret_cast<float4*>(myV);
        #pragma unroll
        for (int q = 0; q < 3; q++) {
            const float4 eq = EQ[q], pq = PQ[q];
            qp[2 * q + 0] = pack2(eq.x + pq.x, eq.y + pq.y);
            qp[2 * q + 1] = pack2(eq.z + pq.z, eq.w + pq.w);
            const float4 ek = EK[q], pk = PK[q];
            kd[q] = make_float4(ek.x + pk.x, ek.y + pk.y, ek.z + pk.z, ek.w + pk.w);
            const float4 ev = EV[q], pv = PV[q];
            vd[q] = make_float4(ev.x + pv.x, ev.y + pv.y, ev.z + pv.z, ev.w + pv.w);
        }
    }
    __syncwarp();   // K/V exchange is intra-warp (4 batches x 8 tokens per warp)

    // ---- causal attention over 8 tokens (LDS.128 + packed f32x2 dots) ----
    const float inv_scale = 0.28867513459481287f;  // 1/sqrt(12)
    float s[SQ];
    float smax = -1e30f;
    #pragma unroll
    for (int m = 0; m < SQ; m++) {
        const ulonglong2* Km = reinterpret_cast<const ulonglong2*>(&sKV[bl * KBAT + m * KSTR]);
        const ulonglong2 k0 = Km[0], k1 = Km[1], k2 = Km[2];
        u64 acc = pack2(0.f, 0.f);
        acc = fma2(qp[0], k0.x, acc);
        acc = fma2(qp[1], k0.y, acc);
        acc = fma2(qp[2], k1.x, acc);
        acc = fma2(qp[3], k1.y, acc);
        acc = fma2(qp[4], k2.x, acc);
        acc = fma2(qp[5], k2.y, acc);
        const float sc = hsum2(acc) * inv_scale;
        s[m] = (m <= n) ? sc : -1e30f;
        smax = fmaxf(smax, s[m]);
    }
    float ssum = 0.f;
    #pragma unroll
    for (int m = 0; m < SQ; m++) {
        s[m] = (m <= n) ? __expf(s[m] - smax) : 0.f;
        ssum += s[m];
    }
    const float rsum = 1.f / ssum;
    u64 ap[ED / 2];
    #pragma unroll
    for (int j = 0; j < ED / 2; j++) ap[j] = pack2(0.f, 0.f);
    #pragma unroll
    for (int m = 0; m < SQ; m++) {
        const float w = s[m] * rsum;
        const u64 ww = pack2(w, w);
        const ulonglong2* Vm = reinterpret_cast<const ulonglong2*>(&sKV[BPB * KBAT + bl * KBAT + m * KSTR]);
        const ulonglong2 v0 = Vm[0], v1 = Vm[1], v2 = Vm[2];
        ap[0] = fma2(ww, v0.x, ap[0]);
        ap[1] = fma2(ww, v0.y, ap[1]);
        ap[2] = fma2(ww, v1.x, ap[2]);
        ap[3] = fma2(ww, v1.y, ap[3]);
        ap[4] = fma2(ww, v2.x, ap[4]);
        ap[5] = fma2(ww, v2.y, ap[5]);
    }

    // ---- output projection (residual), LDS.128 weight rows ----
    #pragma unroll
    for (int i = 0; i < ED; i++) {
        const ulonglong2* wo = reinterpret_cast<const ulonglong2*>(sWo + i * ED);
        const ulonglong2 w0 = wo[0], w1r = wo[1], w2r = wo[2];
        u64 a = pack2(sbo[i], 0.f);
        a = fma2(ap[0], w0.x, a);
        a = fma2(ap[1], w0.y, a);
        a = fma2(ap[2], w1r.x, a);
        a = fma2(ap[3], w1r.y, a);
        a = fma2(ap[4], w2r.x, a);
        a = fma2(ap[5], w2r.y, a);
        X[i] += hsum2(a);
    }

    // ---- FFN (residual), LDS.128 weight rows ----
    u64 xp[ED / 2];
    #pragma unroll
    for (int j = 0; j < ED / 2; j++) xp[j] = pack2(X[2 * j], X[2 * j + 1]);
    float h[FF];
    #pragma unroll
    for (int f = 0; f < FF; f++) {
        const ulonglong2* w1p = reinterpret_cast<const ulonglong2*>(sW1 + f * ED);
        const ulonglong2 a0 = w1p[0], a1 = w1p[1], a2 = w1p[2];
        u64 a = pack2(sb1[f], 0.f);
        a = fma2(xp[0], a0.x, a);
        a = fma2(xp[1], a0.y, a);
        a = fma2(xp[2], a1.x, a);
        a = fma2(xp[3], a1.y, a);
        a = fma2(xp[4], a2.x, a);
        a = fma2(xp[5], a2.y, a);
        h[f] = fmaxf(hsum2(a), 0.f);
    }
    u64 hp[FF / 2];
    #pragma unroll
    for (int j = 0; j < FF / 2; j++) hp[j] = pack2(h[2 * j], h[2 * j + 1]);
    #pragma unroll
    for (int i = 0; i < ED; i++) {
        const ulonglong2* w2p = reinterpret_cast<const ulonglong2*>(sW2 + i * FF);
        u64 a = pack2(sb2[i], 0.f);
        #pragma unroll
        for (int q = 0; q < 6; q++) {
            const ulonglong2 wv = w2p[q];
            a = fma2(hp[2 * q + 0], wv.x, a);
            a = fma2(hp[2 * q + 1], wv.y, a);
        }
        X[i] += hsum2(a);
    }

    // ---- park final X in smem (alias over dead K region) ----
    __syncthreads();                 // everyone done reading K/V
    float* sXf = sKV;                // [256][12], 48 B per token, 16B-aligned rows
    {
        float4* xf = reinterpret_cast<float4*>(sXf) + tid * 3;
        xf[0] = make_float4(X[0], X[1], X[2], X[3]);
        xf[1] = make_float4(X[4], X[5], X[6], X[7]);
        xf[2] = make_float4(X[8], X[9], X[10], X[11]);
    }
    __syncthreads();

    // ---- logits epilogue: thread owns 2 adjacent vocab rows, sweeps 64 tokens ----
    const int v0   = (tid & 63) * 2;     // vocab pair (v0, v0+1)
    const int tseg = tid >> 6;           // token segment [tseg*64, tseg*64+64)
    const float bias0 = sblm[v0], bias1 = sblm[v0 + 1];
    u64 e0[ED / 2], e1[ED / 2];
    {
        const u64* E0 = reinterpret_cast<const u64*>(embed + v0 * ED);
        const u64* E1 = reinterpret_cast<const u64*>(embed + (v0 + 1) * ED);
        #pragma unroll
        for (int j = 0; j < ED / 2; j++) { e0[j] = E0[j]; e1[j] = E1[j]; }
    }

    const size_t rowbase = (size_t)blockIdx.x * (BPB * SQ) + tseg * 64;
    #pragma unroll 4
    for (int k = 0; k < 64; k++) {
        const int t = tseg * 64 + k;
        const ulonglong2* xq = reinterpret_cast<const ulonglong2*>(sXf + t * ED);
        const ulonglong2 x0 = xq[0];   // broadcast LDS.128 (t uniform per warp)
        const ulonglong2 x1 = xq[1];
        const ulonglong2 x2 = xq[2];
        u64 a0 = pack2(bias0, 0.f);
        u64 a1 = pack2(bias1, 0.f);
        a0 = fma2(x0.x, e0[0], a0);  a1 = fma2(x0.x, e1[0], a1);
        a0 = fma2(x0.y, e0[1], a0);  a1 = fma2(x0.y, e1[1], a1);
        a0 = fma2(x1.x, e0[2], a0);  a1 = fma2(x1.x, e1[2], a1);
        a0 = fma2(x1.y, e0[3], a0);  a1 = fma2(x1.y, e1[3], a1);
        a0 = fma2(x2.x, e0[4], a0);  a1 = fma2(x2.x, e1[4], a1);
        a0 = fma2(x2.y, e0[5], a0);  a1 = fma2(x2.y, e1[5], a1);
        float2 r;
        r.x = hsum2(a0);
        r.y = hsum2(a1);
        *reinterpret_cast<float2*>(out + (rowbase + k) * VO + v0) = r;
    }
}

extern "C" void kernel_launch(void* const* d_in, const int* in_sizes, int n_in,
                              void* d_out, int out_size) {
    const int*   x     = (const int*)  d_in[0];
    const float* embed = (const float*)d_in[1];
    const float* pos   = (const float*)d_in[2];
    const float* Wq    = (const float*)d_in[3];
    const float* bq    = (const float*)d_in[4];
    const float* Wk    = (const float*)d_in[5];
    const float* bk    = (const float*)d_in[6];
    const float* Wv    = (const float*)d_in[7];
    const float* bv    = (const float*)d_in[8];
    const float* Wo    = (const float*)d_in[9];
    const float* bo    = (const float*)d_in[10];
    const float* W1    = (const float*)d_in[11];
    const float* b1    = (const float*)d_in[12];
    const float* W2    = (const float*)d_in[13];
    const float* b2    = (const float*)d_in[14];
    const float* blm   = (const float*)d_in[15];
    float* out = (float*)d_out;

    precompute_tables<<<24, 128>>>(embed, pos, Wq, bq, Wk, bk, Wv, bv);

    const int B = in_sizes[0] / SQ;          // 32768
    const int grid = B / BPB;                // 1024 blocks
    tiny_tf_kernel<<<grid, NTHREADS>>>(x, embed, pos,
                                       Wo, bo, W1, b1, W2, b2, blm, out);
}